// round 12
// baseline (speedup 1.0000x reference)
#include <cuda_runtime.h>
#include <cuda_bf16.h>
#include <cstddef>

// Problem constants (dataset-fixed): D=128 feature dim, zeta=2, P=1.
#define DDIM 128
#define YSTRIDE 257

// g_A : raw symmetric A[i][j] = sum_m w_m sp[m][i] sp[m][j] (atomic accum).
// g_AT: folded + transposed: g_AT[j*128+i] = 0 (j<i) | A_ii (j==i) | 2A_ij (j>i).
__device__ float g_A[DDIM * DDIM];
__device__ float g_AT[DDIM * DDIM];

// ---------------------------------------------------------------------------
// Packed f32x2 helpers (sm_103a FFMA2 — 2 fp32 FMAs per instruction).
__device__ __forceinline__ unsigned long long ffma2(unsigned long long a,
                                                    unsigned long long b,
                                                    unsigned long long c) {
    unsigned long long d;
    asm("fma.rn.f32x2 %0, %1, %2, %3;" : "=l"(d) : "l"(a), "l"(b), "l"(c));
    return d;
}
__device__ __forceinline__ unsigned long long pack2(float lo, float hi) {
    unsigned long long r;
    asm("mov.b64 %0, {%1, %2};" : "=l"(r) : "f"(lo), "f"(hi));
    return r;
}
__device__ __forceinline__ void unpack2(float& lo, float& hi,
                                        unsigned long long v) {
    asm("mov.b64 {%0, %1}, %2;" : "=f"(lo), "=f"(hi) : "l"(v));
}

// ---------------------------------------------------------------------------
// Zero g_A and the output (graph replays reuse device globals).
__global__ void zero_kernel(float* out, int s) {
    int i = blockIdx.x * 256 + threadIdx.x;
    if (i < DDIM * DDIM) g_A[i] = 0.f;
    if (i < s) out[i] = 0.f;
}

// ---------------------------------------------------------------------------
// A[i][j] += sum over this block's m-chunk of w_m sp[m][i] sp[m][j].
// Grid: (8 row-tiles, NCHUNK m-chunks). 256 threads = 16 rows x 16 col-groups,
// each thread owns 8 consecutive cols -> 8 register accumulators.
#define NCHUNK 18
__global__ __launch_bounds__(256)
void build_A_kernel(const float* __restrict__ sp,
                    const float* __restrict__ weights,
                    const int* __restrict__ sseg, int M) {
    __shared__ float sps[32][DDIM];
    __shared__ float ws[32];

    const int t = threadIdx.x;
    const int i = (blockIdx.x << 4) + (t >> 4);   // global row 0..127
    const int j0 = (t & 15) << 3;                 // col base 0..120

    const int chunk = (M + NCHUNK - 1) / NCHUNK;
    const int mlo = blockIdx.y * chunk;
    const int mhi = min(M, mlo + chunk);

    float acc[8];
#pragma unroll
    for (int k = 0; k < 8; ++k) acc[k] = 0.f;

    for (int m0 = mlo; m0 < mhi; m0 += 32) {
        const int mc = min(32, mhi - m0);
#pragma unroll
        for (int k = 0; k < 16; ++k) {
            int idx = k * 256 + t;
            int r = idx >> 7, j = idx & 127;
            sps[r][j] = (r < mc) ? sp[(size_t)(m0 + r) * DDIM + j] : 0.f;
        }
        if (t < 32) ws[t] = (t < mc) ? weights[sseg[m0 + t]] : 0.f;
        __syncthreads();

#pragma unroll 4
        for (int r = 0; r < 32; ++r) {
            float a = ws[r] * sps[r][i];
            const float4 b0 = *reinterpret_cast<const float4*>(&sps[r][j0]);
            const float4 b1 = *reinterpret_cast<const float4*>(&sps[r][j0 + 4]);
            acc[0] = fmaf(a, b0.x, acc[0]);
            acc[1] = fmaf(a, b0.y, acc[1]);
            acc[2] = fmaf(a, b0.z, acc[2]);
            acc[3] = fmaf(a, b0.w, acc[3]);
            acc[4] = fmaf(a, b1.x, acc[4]);
            acc[5] = fmaf(a, b1.y, acc[5]);
            acc[6] = fmaf(a, b1.z, acc[6]);
            acc[7] = fmaf(a, b1.w, acc[7]);
        }
        __syncthreads();
    }
#pragma unroll
    for (int k = 0; k < 8; ++k)
        atomicAdd(&g_A[i * DDIM + j0 + k], acc[k]);
}

// ---------------------------------------------------------------------------
// Fold symmetry and transpose: g_AT[j*128+i] = Afold[i][j].
__global__ void fold_kernel() {
    int idx = blockIdx.x * 256 + threadIdx.x;     // coalesced read of g_A
    int i = idx >> 7, j = idx & 127;
    float v = g_A[idx];
    float f = (j < i) ? 0.f : ((j == i) ? v : 2.f * v);
    g_AT[j * DDIM + i] = f;
}

// ---------------------------------------------------------------------------
// quad: per atom a, q = y^T Afold y / ||y||^2, atomicAdd to out[aseg[a]].
//
// 256 threads, 256 atoms/block. Warp w handles i-tiles {w, 15-w} (k-trips sum
// to 136 for every warp). Each lane owns 8 atoms (a = lane + 32c). Per k-step:
// 2 uniform LDS.128 of AshT (8 i-values), 8 LDS.32 of Y, 32 FFMA2 — each A
// load amortized over 8 atoms, crossbar traffic 10 wavefronts / 256 MACs.
__global__ __launch_bounds__(256, 1)
void quad_kernel(const float* __restrict__ ps, const int* __restrict__ aseg,
                 float* __restrict__ out, int N) {
    extern __shared__ float sh[];
    float* AshT = sh;                          // 16384 floats: [k][i]
    float* Ysh  = sh + DDIM * DDIM;            // 128 * 257:   [j][atom]
    float* q_s  = Ysh + DDIM * YSTRIDE;        // 256 partial sums

    const int t = threadIdx.x;
    const int w = t >> 5;                      // warp 0..7
    const int l = t & 31;                      // lane

    // Stage folded-transposed A (coalesced, conflict-free).
    for (int idx = t; idx < DDIM * DDIM; idx += 256) AshT[idx] = g_AT[idx];
    q_s[t] = 0.f;

    const int base = blockIdx.x * 256;
    // Coalesced gmem read, transposed conflict-free smem write (stride 257).
#pragma unroll 4
    for (int k = 0; k < 128; ++k) {
        int idx = k * 256 + t;
        int al = idx >> 7;        // local atom (warp-uniform)
        int j  = idx & 127;       // feature index (consecutive in warp)
        int ga = base + al;
        Ysh[j * YSTRIDE + al] = (ga < N) ? ps[(size_t)ga * DDIM + j] : 0.f;
    }
    __syncthreads();

    float qp[8];
#pragma unroll
    for (int c = 0; c < 8; ++c) qp[c] = 0.f;

#pragma unroll
    for (int tt = 0; tt < 2; ++tt) {
        const int ti = tt ? (15 - w) : w;
        const int i0 = ti << 3;

        unsigned long long z[8][4];
#pragma unroll
        for (int c = 0; c < 8; ++c)
#pragma unroll
            for (int p = 0; p < 4; ++p) z[c][p] = 0ull;

        // Triangular: Afold[i][k] = 0 for k < i, so k starts at i0.
#pragma unroll 2
        for (int k = i0; k < DDIM; ++k) {
            const ulonglong2* Ak =
                reinterpret_cast<const ulonglong2*>(AshT + k * DDIM + i0);
            const ulonglong2 a01 = Ak[0];      // (a_i0,a_i1) (a_i2,a_i3)
            const ulonglong2 a23 = Ak[1];      // (a_i4,a_i5) (a_i6,a_i7)
            const float* yk = Ysh + k * YSTRIDE + l;
#pragma unroll
            for (int c = 0; c < 8; ++c) {
                float y = yk[c * 32];
                unsigned long long yy = pack2(y, y);
                z[c][0] = ffma2(a01.x, yy, z[c][0]);
                z[c][1] = ffma2(a01.y, yy, z[c][1]);
                z[c][2] = ffma2(a23.x, yy, z[c][2]);
                z[c][3] = ffma2(a23.y, yy, z[c][3]);
            }
        }

        // q contribution: sum_i y_i * z_i over this tile's 8 i's.
#pragma unroll
        for (int p = 0; p < 4; ++p) {
            const int i = i0 + 2 * p;
            const float* y0 = Ysh + i * YSTRIDE + l;
            const float* y1 = y0 + YSTRIDE;
#pragma unroll
            for (int c = 0; c < 8; ++c) {
                float zlo, zhi;
                unpack2(zlo, zhi, z[c][p]);
                qp[c] = fmaf(y0[c * 32], zlo, qp[c]);
                qp[c] = fmaf(y1[c * 32], zhi, qp[c]);
            }
        }
    }

    // Reduce across warps (each warp produced partials for all 256 atoms).
#pragma unroll
    for (int c = 0; c < 8; ++c) atomicAdd(&q_s[l + 32 * c], qp[c]);
    __syncthreads();

    const int a = base + t;
    if (a >= N) return;

    // Squared norm of atom t (normalization folds into the quadratic form).
    const float* Yt = Ysh + t;
    float n2 = 0.f;
#pragma unroll
    for (int j = 0; j < DDIM; j += 4) {
        float v0 = Yt[(j + 0) * YSTRIDE];
        float v1 = Yt[(j + 1) * YSTRIDE];
        float v2 = Yt[(j + 2) * YSTRIDE];
        float v3 = Yt[(j + 3) * YSTRIDE];
        n2 = fmaf(v0, v0, n2);
        n2 = fmaf(v1, v1, n2);
        n2 = fmaf(v2, v2, n2);
        n2 = fmaf(v3, v3, n2);
    }

    atomicAdd(&out[aseg[a]], q_s[t] / n2);
}

// ---------------------------------------------------------------------------
extern "C" void kernel_launch(void* const* d_in, const int* in_sizes, int n_in,
                              void* d_out, int out_size) {
    const float* ps   = (const float*)d_in[0];   // [N, 128]
    const float* sp   = (const float*)d_in[1];   // [M, 128] (unit rows)
    const float* wts  = (const float*)d_in[2];   // [1, T]
    const int*   aseg = (const int*)d_in[3];     // [N] sorted
    const int*   sseg = (const int*)d_in[4];     // [M] sorted

    const int N = in_sizes[3];
    const int M = in_sizes[4];
    float* out = (float*)d_out;
    const int S = out_size;                      // P == 1

    const int smem =
        (DDIM * DDIM + DDIM * YSTRIDE + 256) * (int)sizeof(float); // 198144
    cudaFuncSetAttribute(quad_kernel,
                         cudaFuncAttributeMaxDynamicSharedMemorySize, smem);

    int zgrid = (DDIM * DDIM > S ? DDIM * DDIM : S);
    zero_kernel<<<(zgrid + 255) / 256, 256>>>(out, S);
    build_A_kernel<<<dim3(8, NCHUNK), 256>>>(sp, wts, sseg, M);
    fold_kernel<<<DDIM * DDIM / 256, 256>>>();
    quad_kernel<<<(N + 255) / 256, 256, smem>>>(ps, aseg, out, N);
}

// round 13
// speedup vs baseline: 1.0053x; 1.0053x over previous
#include <cuda_runtime.h>
#include <cuda_bf16.h>
#include <cstddef>

// Problem constants (dataset-fixed): D=128 feature dim, zeta=2, P=1.
#define DDIM 128
#define YSTRIDE 257

// g_A : raw symmetric A[i][j] = sum_m w_m sp[m][i] sp[m][j] (atomic accum).
// g_AT: folded + transposed: g_AT[j*128+i] = 0 (j<i) | A_ii (j==i) | 2A_ij (j>i).
__device__ float g_A[DDIM * DDIM];
__device__ float g_AT[DDIM * DDIM];

// ---------------------------------------------------------------------------
// Packed f32x2 helpers (sm_103a FFMA2 — 2 fp32 FMAs per instruction).
__device__ __forceinline__ unsigned long long ffma2(unsigned long long a,
                                                    unsigned long long b,
                                                    unsigned long long c) {
    unsigned long long d;
    asm("fma.rn.f32x2 %0, %1, %2, %3;" : "=l"(d) : "l"(a), "l"(b), "l"(c));
    return d;
}
__device__ __forceinline__ unsigned long long pack2(float lo, float hi) {
    unsigned long long r;
    asm("mov.b64 %0, {%1, %2};" : "=l"(r) : "f"(lo), "f"(hi));
    return r;
}
__device__ __forceinline__ void unpack2(float& lo, float& hi,
                                        unsigned long long v) {
    asm("mov.b64 {%0, %1}, %2;" : "=f"(lo), "=f"(hi) : "l"(v));
}

// ---------------------------------------------------------------------------
// Zero g_A and the output (graph replays reuse device globals).
__global__ void zero_kernel(float* out, int s) {
    int i = blockIdx.x * 256 + threadIdx.x;
    if (i < DDIM * DDIM) g_A[i] = 0.f;
    if (i < s) out[i] = 0.f;
}

// ---------------------------------------------------------------------------
// A[i][j] += sum over this block's m-chunk of w_m sp[m][i] sp[m][j].
// Grid: (8 row-tiles, NCHUNK m-chunks). 256 threads = 16 rows x 16 col-groups,
// each thread owns 8 consecutive cols -> 8 register accumulators.
#define NCHUNK 18
__global__ __launch_bounds__(256)
void build_A_kernel(const float* __restrict__ sp,
                    const float* __restrict__ weights,
                    const int* __restrict__ sseg, int M) {
    __shared__ float sps[32][DDIM];
    __shared__ float ws[32];

    const int t = threadIdx.x;
    const int i = (blockIdx.x << 4) + (t >> 4);   // global row 0..127
    const int j0 = (t & 15) << 3;                 // col base 0..120

    const int chunk = (M + NCHUNK - 1) / NCHUNK;
    const int mlo = blockIdx.y * chunk;
    const int mhi = min(M, mlo + chunk);

    float acc[8];
#pragma unroll
    for (int k = 0; k < 8; ++k) acc[k] = 0.f;

    for (int m0 = mlo; m0 < mhi; m0 += 32) {
        const int mc = min(32, mhi - m0);
#pragma unroll
        for (int k = 0; k < 16; ++k) {
            int idx = k * 256 + t;
            int r = idx >> 7, j = idx & 127;
            sps[r][j] = (r < mc) ? sp[(size_t)(m0 + r) * DDIM + j] : 0.f;
        }
        if (t < 32) ws[t] = (t < mc) ? weights[sseg[m0 + t]] : 0.f;
        __syncthreads();

#pragma unroll 4
        for (int r = 0; r < 32; ++r) {
            float a = ws[r] * sps[r][i];
            const float4 b0 = *reinterpret_cast<const float4*>(&sps[r][j0]);
            const float4 b1 = *reinterpret_cast<const float4*>(&sps[r][j0 + 4]);
            acc[0] = fmaf(a, b0.x, acc[0]);
            acc[1] = fmaf(a, b0.y, acc[1]);
            acc[2] = fmaf(a, b0.z, acc[2]);
            acc[3] = fmaf(a, b0.w, acc[3]);
            acc[4] = fmaf(a, b1.x, acc[4]);
            acc[5] = fmaf(a, b1.y, acc[5]);
            acc[6] = fmaf(a, b1.z, acc[6]);
            acc[7] = fmaf(a, b1.w, acc[7]);
        }
        __syncthreads();
    }
#pragma unroll
    for (int k = 0; k < 8; ++k)
        atomicAdd(&g_A[i * DDIM + j0 + k], acc[k]);
}

// ---------------------------------------------------------------------------
// Fold symmetry and transpose: g_AT[j*128+i] = Afold[i][j].
__global__ void fold_kernel() {
    int idx = blockIdx.x * 256 + threadIdx.x;     // coalesced read of g_A
    int i = idx >> 7, j = idx & 127;
    float v = g_A[idx];
    float f = (j < i) ? 0.f : ((j == i) ? v : 2.f * v);
    g_AT[j * DDIM + i] = f;
}

// ---------------------------------------------------------------------------
// quad: per atom a, q = y^T Afold y / ||y||^2, atomicAdd to out[aseg[a]].
//
// 256 threads, 256 atoms/block. Warp w handles i-tiles {w, 15-w} (k-trips sum
// to 136 for every warp). Each lane owns 8 atoms (a = lane + 32c). Per k-step:
// 2 uniform LDS.128 of AshT (8 i-values), 8 LDS.32 of Y, 32 FFMA2 — each A
// load amortized over 8 atoms, crossbar traffic 10 wavefronts / 256 MACs.
__global__ __launch_bounds__(256, 1)
void quad_kernel(const float* __restrict__ ps, const int* __restrict__ aseg,
                 float* __restrict__ out, int N) {
    extern __shared__ float sh[];
    float* AshT = sh;                          // 16384 floats: [k][i]
    float* Ysh  = sh + DDIM * DDIM;            // 128 * 257:   [j][atom]
    float* q_s  = Ysh + DDIM * YSTRIDE;        // 256 partial sums

    const int t = threadIdx.x;
    const int w = t >> 5;                      // warp 0..7
    const int l = t & 31;                      // lane

    // Stage folded-transposed A (coalesced, conflict-free).
    for (int idx = t; idx < DDIM * DDIM; idx += 256) AshT[idx] = g_AT[idx];
    q_s[t] = 0.f;

    const int base = blockIdx.x * 256;
    // Coalesced gmem read, transposed conflict-free smem write (stride 257).
#pragma unroll 4
    for (int k = 0; k < 128; ++k) {
        int idx = k * 256 + t;
        int al = idx >> 7;        // local atom (warp-uniform)
        int j  = idx & 127;       // feature index (consecutive in warp)
        int ga = base + al;
        Ysh[j * YSTRIDE + al] = (ga < N) ? ps[(size_t)ga * DDIM + j] : 0.f;
    }
    __syncthreads();

    float qp[8];
#pragma unroll
    for (int c = 0; c < 8; ++c) qp[c] = 0.f;

#pragma unroll
    for (int tt = 0; tt < 2; ++tt) {
        const int ti = tt ? (15 - w) : w;
        const int i0 = ti << 3;

        unsigned long long z[8][4];
#pragma unroll
        for (int c = 0; c < 8; ++c)
#pragma unroll
            for (int p = 0; p < 4; ++p) z[c][p] = 0ull;

        // Triangular: Afold[i][k] = 0 for k < i, so k starts at i0.
#pragma unroll 2
        for (int k = i0; k < DDIM; ++k) {
            const ulonglong2* Ak =
                reinterpret_cast<const ulonglong2*>(AshT + k * DDIM + i0);
            const ulonglong2 a01 = Ak[0];      // (a_i0,a_i1) (a_i2,a_i3)
            const ulonglong2 a23 = Ak[1];      // (a_i4,a_i5) (a_i6,a_i7)
            const float* yk = Ysh + k * YSTRIDE + l;
#pragma unroll
            for (int c = 0; c < 8; ++c) {
                float y = yk[c * 32];
                unsigned long long yy = pack2(y, y);
                z[c][0] = ffma2(a01.x, yy, z[c][0]);
                z[c][1] = ffma2(a01.y, yy, z[c][1]);
                z[c][2] = ffma2(a23.x, yy, z[c][2]);
                z[c][3] = ffma2(a23.y, yy, z[c][3]);
            }
        }

        // q contribution: sum_i y_i * z_i over this tile's 8 i's.
#pragma unroll
        for (int p = 0; p < 4; ++p) {
            const int i = i0 + 2 * p;
            const float* y0 = Ysh + i * YSTRIDE + l;
            const float* y1 = y0 + YSTRIDE;
#pragma unroll
            for (int c = 0; c < 8; ++c) {
                float zlo, zhi;
                unpack2(zlo, zhi, z[c][p]);
                qp[c] = fmaf(y0[c * 32], zlo, qp[c]);
                qp[c] = fmaf(y1[c * 32], zhi, qp[c]);
            }
        }
    }

    // Reduce across warps (each warp produced partials for all 256 atoms).
#pragma unroll
    for (int c = 0; c < 8; ++c) atomicAdd(&q_s[l + 32 * c], qp[c]);
    __syncthreads();

    const int a = base + t;
    if (a >= N) return;

    // Squared norm of atom t (normalization folds into the quadratic form).
    const float* Yt = Ysh + t;
    float n2 = 0.f;
#pragma unroll
    for (int j = 0; j < DDIM; j += 4) {
        float v0 = Yt[(j + 0) * YSTRIDE];
        float v1 = Yt[(j + 1) * YSTRIDE];
        float v2 = Yt[(j + 2) * YSTRIDE];
        float v3 = Yt[(j + 3) * YSTRIDE];
        n2 = fmaf(v0, v0, n2);
        n2 = fmaf(v1, v1, n2);
        n2 = fmaf(v2, v2, n2);
        n2 = fmaf(v3, v3, n2);
    }

    atomicAdd(&out[aseg[a]], q_s[t] / n2);
}

// ---------------------------------------------------------------------------
extern "C" void kernel_launch(void* const* d_in, const int* in_sizes, int n_in,
                              void* d_out, int out_size) {
    const float* ps   = (const float*)d_in[0];   // [N, 128]
    const float* sp   = (const float*)d_in[1];   // [M, 128] (unit rows)
    const float* wts  = (const float*)d_in[2];   // [1, T]
    const int*   aseg = (const int*)d_in[3];     // [N] sorted
    const int*   sseg = (const int*)d_in[4];     // [M] sorted

    const int N = in_sizes[3];
    const int M = in_sizes[4];
    float* out = (float*)d_out;
    const int S = out_size;                      // P == 1

    const int smem =
        (DDIM * DDIM + DDIM * YSTRIDE + 256) * (int)sizeof(float); // 198144
    cudaFuncSetAttribute(quad_kernel,
                         cudaFuncAttributeMaxDynamicSharedMemorySize, smem);

    int zgrid = (DDIM * DDIM > S ? DDIM * DDIM : S);
    zero_kernel<<<(zgrid + 255) / 256, 256>>>(out, S);
    build_A_kernel<<<dim3(8, NCHUNK), 256>>>(sp, wts, sseg, M);
    fold_kernel<<<DDIM * DDIM / 256, 256>>>();
    quad_kernel<<<(N + 255) / 256, 256, smem>>>(ps, aseg, out, N);
}